// round 6
// baseline (speedup 1.0000x reference)
#include <cuda_runtime.h>
#include <cuda_fp16.h>
#include <math.h>
#include <stdint.h>

#define C     64
#define A     128
#define HID   256
#define NA    4
#define HW    512
#define NPOS  (HW * HW)
#define TM    128
#define NTILES (NPOS / TM)       // 2048
#define GRID  296                // 2 CTAs per SM
#define NTHREADS 256

// ---- dynamic SMEM byte offsets (fragment-packed fp16 operands) ----
#define OFF_IMG   0              // 4 ks * 8 mt * 512  = 16384 B
#define OFF_FEAT  16384          // 8 ks * 8 mt * 512  = 32768 B
#define OFF_B1    49152          // 4 ks * 16 nt * 256 = 16384 B
#define OFF_B2    65536          // 8 ks * 16 nt * 256 = 32768 B
#define OFF_TAIL  98304
#define TF_BASE   (OFF_TAIL / 4)
#define TI_RED    (TF_BASE + 0)      // 8
#define TI_CB     (TF_BASE + 16)     // 128
#define TI_IB     (TF_BASE + 144)    // 128
#define TI_FW     (TF_BASE + 272)    // 128
#define TI_SCORE  (TF_BASE + 400)    // 128 (reused as merge half-1)
#define TI_WEXP   (TF_BASE + 528)    // 128
#define TI_ACC    (TF_BASE + 656)    // 128 (reused as merge att)
#define TI_SX     (TF_BASE + 784)    // 256 (reused as merge h)
#define TI_SH     (TF_BASE + 1040)   // 256
#define SMEM_BYTES (OFF_TAIL + 1296 * 4)

__device__ float g_l[GRID];
__device__ float g_acc[GRID * A];
__device__ float g_gates[4 * HID];
__device__ unsigned int g_cnt;       // zero-init; last CTA resets after merge

__device__ __forceinline__ void mma16(float* c, const uint32_t* a, const uint32_t* b) {
    asm volatile("mma.sync.aligned.m16n8k16.row.col.f32.f16.f16.f32 "
        "{%0,%1,%2,%3}, {%4,%5,%6,%7}, {%8,%9}, {%0,%1,%2,%3};"
        : "+f"(c[0]), "+f"(c[1]), "+f"(c[2]), "+f"(c[3])
        : "r"(a[0]), "r"(a[1]), "r"(a[2]), "r"(a[3]), "r"(b[0]), "r"(b[1]));
}

__device__ __forceinline__ uint32_t h2(float lo, float hi) {
    __half2 v = __floats2half2_rn(lo, hi);
    return *reinterpret_cast<uint32_t*>(&v);
}

// ---------------------------------------------------------------------------
// Persistent fused kernel: fp16 dual GEMM + softmax-weighted pooling.
// 296 CTAs (2/SM). Blocks 0..127 also compute LSTM gate rows; the last CTA
// to finish does the global merge + LSTM activations + logits.
// ---------------------------------------------------------------------------
__global__ void __launch_bounds__(NTHREADS, 2)
attn_kernel(const float* __restrict__ img,
            const float* __restrict__ conv_w, const float* __restrict__ conv_b,
            const float* __restrict__ ia_w,   const float* __restrict__ ia_b,
            const float* __restrict__ fa_w,
            const float* __restrict__ action, const float* __restrict__ h0,
            const float* __restrict__ ae_w,   const float* __restrict__ ae_b,
            const float* __restrict__ w_ih,   const float* __restrict__ w_hh,
            const float* __restrict__ b_ih,   const float* __restrict__ b_hh,
            const float* __restrict__ c0,     const float* __restrict__ actor_w,
            const float* __restrict__ actor_b, float* __restrict__ out)
{
    extern __shared__ __align__(1024) float sm[];
    char* smc = (char*)sm;
    __shared__ unsigned int s_isLast;

    const int tid    = threadIdx.x;
    const int lane   = tid & 31;
    const int wid    = tid >> 5;
    const int g      = lane >> 2;
    const int tig    = lane & 3;
    const int warp_m = wid & 3;
    const int warp_n = wid >> 2;

    // ---- one-time: pack B1 (conv_w [128n x 64k]) fragments, fp16 ----
    for (int idx = tid; idx < 4 * 16 * 32 * 2; idx += NTHREADS) {
        int r = idx & 1, l = (idx >> 1) & 31, nt = (idx >> 6) & 15, ks = idx >> 10;
        int n = nt * 8 + (l >> 2);
        int k0 = ks * 16 + (l & 3) * 2 + r * 8;
        *(uint32_t*)(smc + OFF_B1 + (ks * 16 + nt) * 256 + l * 8 + r * 4) =
            h2(conv_w[n * C + k0], conv_w[n * C + k0 + 1]);
    }
    // ---- pack B2 (ia_w [128n x 128k]) ----
    for (int idx = tid; idx < 8 * 16 * 32 * 2; idx += NTHREADS) {
        int r = idx & 1, l = (idx >> 1) & 31, nt = (idx >> 6) & 15, ks = idx >> 10;
        int n = nt * 8 + (l >> 2);
        int k0 = ks * 16 + (l & 3) * 2 + r * 8;
        *(uint32_t*)(smc + OFF_B2 + (ks * 16 + nt) * 256 + l * 8 + r * 4) =
            h2(ia_w[n * A + k0], ia_w[n * A + k0 + 1]);
    }
    if (tid < A) {
        sm[TI_CB + tid] = conv_b[tid];
        sm[TI_IB + tid] = ia_b[tid];
        sm[TI_FW + tid] = fa_w[tid];
        sm[TI_ACC + tid] = 0.f;
    }
    if (blockIdx.x < 128) {     // gates: x = ae(action) + ae_b, stash h0
        float a0 = action[0], a1 = action[1], a2 = action[2], a3 = action[3];
        sm[TI_SX + tid] = ae_b[tid] + a0 * ae_w[tid * 4] + a1 * ae_w[tid * 4 + 1]
                                    + a2 * ae_w[tid * 4 + 2] + a3 * ae_w[tid * 4 + 3];
        sm[TI_SH + tid] = h0[tid];
    }
    __syncthreads();

    // ---- folded LSTM gates: one row per warp for blocks < 128 ----
    if (blockIdx.x < 128) {
        int r = blockIdx.x * 8 + wid;
        const float4* wi = (const float4*)(w_ih + (size_t)r * HID);
        const float4* wh = (const float4*)(w_hh + (size_t)r * HID);
        float s = 0.f;
        #pragma unroll
        for (int j = 0; j < 2; ++j) {
            float4 u = wi[lane * 2 + j], v = wh[lane * 2 + j];
            int k = lane * 8 + j * 4;
            s += u.x * sm[TI_SX + k] + u.y * sm[TI_SX + k + 1]
               + u.z * sm[TI_SX + k + 2] + u.w * sm[TI_SX + k + 3];
            s += v.x * sm[TI_SH + k] + v.y * sm[TI_SH + k + 1]
               + v.z * sm[TI_SH + k + 2] + v.w * sm[TI_SH + k + 3];
        }
        #pragma unroll
        for (int off = 16; off; off >>= 1) s += __shfl_xor_sync(0xffffffffu, s, off);
        if (lane == 0) g_gates[r] = s + b_ih[r] + b_hh[r];
    }

    // staging mapping: thread owns position sp, channels sch*32..+31
    const int sp  = tid & 127, sch = tid >> 7;
    const int smt = sp >> 4, sg = sp & 7, srh = (sp >> 3) & 1;

    float attreg[8][2];
    #pragma unroll
    for (int i = 0; i < 8; ++i) { attreg[i][0] = 0.f; attreg[i][1] = 0.f; }
    float l_run = 0.f;   // only tid==0's copy is used

    // prologue prefetch (tile blockIdx.x), converted to half2 at load
    uint32_t rimg[16];
    {
        const float* srcb = img + (size_t)(sch * 32) * NPOS + (size_t)blockIdx.x * TM + sp;
        #pragma unroll
        for (int j = 0; j < 16; ++j)
            rimg[j] = h2(srcb[(size_t)(2 * j) * NPOS], srcb[(size_t)(2 * j + 1) * NPOS]);
    }

    for (int t = blockIdx.x; t < NTILES; t += GRID) {
        // ---- stage img tile into fp16 A fragments ----
        #pragma unroll
        for (int j = 0; j < 16; ++j) {
            int ks  = sch * 2 + (j >> 3);
            int tg  = j & 3;
            int hb  = (j >> 2) & 1;
            int reg = srh + 2 * hb;
            *(uint32_t*)(smc + OFF_IMG + (ks * 8 + smt) * 512 + (sg * 4 + tg) * 16 + reg * 4) =
                rimg[j];
        }
        if (tid < TM) sm[TI_SCORE + tid] = 0.f;
        __syncthreads();                                   // sync 1

        // prefetch next tile (hidden under both GEMMs)
        int t2 = t + GRID;
        if (t2 < NTILES) {
            const float* srcb = img + (size_t)(sch * 32) * NPOS + (size_t)t2 * TM + sp;
            #pragma unroll
            for (int j = 0; j < 16; ++j)
                rimg[j] = h2(srcb[(size_t)(2 * j) * NPOS], srcb[(size_t)(2 * j + 1) * NPOS]);
        }

        // ---- GEMM1: feat = img @ conv_w^T  (K=64; 4 k16-steps) ----
        float acc[2][8][4];
        #pragma unroll
        for (int mt = 0; mt < 2; ++mt)
            #pragma unroll
            for (int nt = 0; nt < 8; ++nt)
                #pragma unroll
                for (int r = 0; r < 4; ++r) acc[mt][nt][r] = 0.f;

        #pragma unroll
        for (int ks = 0; ks < 4; ++ks) {
            uint32_t a[2][4];
            #pragma unroll
            for (int mt = 0; mt < 2; ++mt) {
                uint4 v = *(const uint4*)(smc + OFF_IMG +
                    (ks * 8 + warp_m * 2 + mt) * 512 + lane * 16);
                a[mt][0] = v.x; a[mt][1] = v.y; a[mt][2] = v.z; a[mt][3] = v.w;
            }
            #pragma unroll
            for (int nt = 0; nt < 8; ++nt) {
                uint2 b = *(const uint2*)(smc + OFF_B1 +
                    (ks * 16 + warp_n * 8 + nt) * 256 + lane * 8);
                uint32_t bb[2] = {b.x, b.y};
                mma16(acc[0][nt], a[0], bb);
                mma16(acc[1][nt], a[1], bb);
            }
        }

        // ---- epilogue 1: bias+relu; own-lane identity repack to fp16 FEAT ----
        #pragma unroll
        for (int mt = 0; mt < 2; ++mt) {
            #pragma unroll
            for (int nt = 0; nt < 8; ++nt) {
                float b0 = sm[TI_CB + warp_n * 64 + nt * 8 + tig * 2];
                float b1 = sm[TI_CB + warp_n * 64 + nt * 8 + tig * 2 + 1];
                acc[mt][nt][0] = fmaxf(acc[mt][nt][0] + b0, 0.f);
                acc[mt][nt][1] = fmaxf(acc[mt][nt][1] + b1, 0.f);
                acc[mt][nt][2] = fmaxf(acc[mt][nt][2] + b0, 0.f);
                acc[mt][nt][3] = fmaxf(acc[mt][nt][3] + b1, 0.f);
            }
            #pragma unroll
            for (int k2 = 0; k2 < 4; ++k2) {
                uint4 v;
                v.x = h2(acc[mt][k2 * 2][0],     acc[mt][k2 * 2][1]);
                v.y = h2(acc[mt][k2 * 2][2],     acc[mt][k2 * 2][3]);
                v.z = h2(acc[mt][k2 * 2 + 1][0], acc[mt][k2 * 2 + 1][1]);
                v.w = h2(acc[mt][k2 * 2 + 1][2], acc[mt][k2 * 2 + 1][3]);
                *(uint4*)(smc + OFF_FEAT +
                    ((warp_n * 4 + k2) * 8 + warp_m * 2 + mt) * 512 + lane * 16) = v;
            }
        }
        __syncthreads();                                   // sync 2

        // ---- GEMM2: att1 = feat @ ia_w^T  (K=128; 8 k16-steps) ----
        // acc is REUSED (feat regs dead; pooling re-reads fp16 FEAT later)
        #pragma unroll
        for (int mt = 0; mt < 2; ++mt)
            #pragma unroll
            for (int nt = 0; nt < 8; ++nt)
                #pragma unroll
                for (int r = 0; r < 4; ++r) acc[mt][nt][r] = 0.f;

        #pragma unroll
        for (int ks = 0; ks < 8; ++ks) {
            uint32_t a[2][4];
            #pragma unroll
            for (int mt = 0; mt < 2; ++mt) {
                uint4 v = *(const uint4*)(smc + OFF_FEAT +
                    (ks * 8 + warp_m * 2 + mt) * 512 + lane * 16);
                a[mt][0] = v.x; a[mt][1] = v.y; a[mt][2] = v.z; a[mt][3] = v.w;
            }
            #pragma unroll
            for (int nt = 0; nt < 8; ++nt) {
                uint2 b = *(const uint2*)(smc + OFF_B2 +
                    (ks * 16 + warp_n * 8 + nt) * 256 + lane * 8);
                uint32_t bb[2] = {b.x, b.y};
                mma16(acc[0][nt], a[0], bb);
                mma16(acc[1][nt], a[1], bb);
            }
        }

        // ---- scores: s[p] = sum_j relu(att1 + ia_b) * fa_w ----
        #pragma unroll
        for (int mt = 0; mt < 2; ++mt) {
            #pragma unroll
            for (int rh = 0; rh < 2; ++rh) {
                float s = 0.f;
                #pragma unroll
                for (int nt = 0; nt < 8; ++nt) {
                    #pragma unroll
                    for (int cc = 0; cc < 2; ++cc) {
                        int n = warp_n * 64 + nt * 8 + tig * 2 + cc;
                        s += fmaxf(acc[mt][nt][rh * 2 + cc] + sm[TI_IB + n], 0.f) * sm[TI_FW + n];
                    }
                }
                s += __shfl_xor_sync(0xffffffffu, s, 1);
                s += __shfl_xor_sync(0xffffffffu, s, 2);
                if (tig == 0)
                    atomicAdd(&sm[TI_SCORE + (warp_m * 2 + mt) * 16 + g + 8 * rh], s);
            }
        }
        __syncthreads();                                   // sync 3

        // ---- max-free softmax weights (scores bounded far below exp overflow) ----
        if (tid < TM) {
            float w = expf(sm[TI_SCORE + tid]);
            sm[TI_WEXP + tid] = w;
            #pragma unroll
            for (int off = 16; off; off >>= 1)
                w += __shfl_xor_sync(0xffffffffu, w, off);
            if (lane == 0) sm[TI_RED + wid] = w;
        }
        __syncthreads();                                   // sync 4
        if (tid == 0)
            l_run += sm[TI_RED] + sm[TI_RED + 1] + sm[TI_RED + 2] + sm[TI_RED + 3];

        // ---- attention pooling: re-read fp16 FEAT fragments (own lane) ----
        {
            float wx[2][2];
            #pragma unroll
            for (int mt = 0; mt < 2; ++mt)
                #pragma unroll
                for (int rh = 0; rh < 2; ++rh)
                    wx[mt][rh] = sm[TI_WEXP + (warp_m * 2 + mt) * 16 + g + 8 * rh];

            float part[8][2];
            #pragma unroll
            for (int i = 0; i < 8; ++i) { part[i][0] = 0.f; part[i][1] = 0.f; }

            #pragma unroll
            for (int mt = 0; mt < 2; ++mt) {
                #pragma unroll
                for (int k2 = 0; k2 < 4; ++k2) {
                    uint4 v = *(const uint4*)(smc + OFF_FEAT +
                        ((warp_n * 4 + k2) * 8 + warp_m * 2 + mt) * 512 + lane * 16);
                    float2 f;
                    f = __half22float2(*(__half2*)&v.x);   // nt=k2*2, rh0
                    part[k2 * 2][0] += wx[mt][0] * f.x;
                    part[k2 * 2][1] += wx[mt][0] * f.y;
                    f = __half22float2(*(__half2*)&v.y);   // nt=k2*2, rh1
                    part[k2 * 2][0] += wx[mt][1] * f.x;
                    part[k2 * 2][1] += wx[mt][1] * f.y;
                    f = __half22float2(*(__half2*)&v.z);   // nt=k2*2+1, rh0
                    part[k2 * 2 + 1][0] += wx[mt][0] * f.x;
                    part[k2 * 2 + 1][1] += wx[mt][0] * f.y;
                    f = __half22float2(*(__half2*)&v.w);   // nt=k2*2+1, rh1
                    part[k2 * 2 + 1][0] += wx[mt][1] * f.x;
                    part[k2 * 2 + 1][1] += wx[mt][1] * f.y;
                }
            }
            #pragma unroll
            for (int nt = 0; nt < 8; ++nt) {
                #pragma unroll
                for (int cc = 0; cc < 2; ++cc) {
                    float v = part[nt][cc];
                    v += __shfl_xor_sync(0xffffffffu, v, 4);
                    v += __shfl_xor_sync(0xffffffffu, v, 8);
                    v += __shfl_xor_sync(0xffffffffu, v, 16);
                    attreg[nt][cc] += v;
                }
            }
        }
        // no trailing sync: next-tile writers to s_score/s_wexp are ordered
        // behind sync 3/4, which readers here have already passed; FEAT is
        // next written after the next tile's sync 2.
    }

    // ---- CTA epilogue: combine warp attregs, emit partials ----
    __syncthreads();
    if (g == 0) {   // lanes 0..3 hold the g-reduced sums; tig = lane
        #pragma unroll
        for (int nt = 0; nt < 8; ++nt) {
            #pragma unroll
            for (int cc = 0; cc < 2; ++cc)
                atomicAdd(&sm[TI_ACC + warp_n * 64 + nt * 8 + tig * 2 + cc], attreg[nt][cc]);
        }
    }
    __syncthreads();
    if (tid < A) g_acc[blockIdx.x * A + tid] = sm[TI_ACC + tid];
    if (tid == 0) g_l[blockIdx.x] = l_run;

    // ---- last-CTA merge: softmax normalize + LSTM + logits ----
    __threadfence();
    __syncthreads();
    if (tid == 0) s_isLast = (atomicAdd(&g_cnt, 1u) == GRID - 1);
    __syncthreads();
    if (!s_isLast) return;
    __threadfence();

    // L = sum g_l
    if (wid == 0) {
        float l = 0.f;
        for (int b = lane; b < GRID; b += 32) l += g_l[b];
        #pragma unroll
        for (int off = 16; off; off >>= 1)
            l += __shfl_xor_sync(0xffffffffu, l, off);
        if (lane == 0) sm[TI_RED] = l;
    }
    // half-column partial sums of g_acc (2 threads per column, MLP-rich)
    {
        int a = tid & 127, hh = tid >> 7;
        const float* src = g_acc + (size_t)(hh * (GRID / 2)) * A + a;
        float p = 0.f;
        #pragma unroll 4
        for (int b = 0; b < GRID / 2; ++b) p += src[(size_t)b * A];
        sm[(hh ? TI_SCORE : TI_ACC) + a] = p;
    }
    // LSTM activations from g_gates
    {
        float ig = g_gates[tid];
        float fg = g_gates[HID + tid];
        float gg = g_gates[2 * HID + tid];
        float og = g_gates[3 * HID + tid];
        float si = 1.f / (1.f + expf(-ig));
        float sf = 1.f / (1.f + expf(-fg));
        float so = 1.f / (1.f + expf(-og));
        float cc = sf * c0[tid] + si * tanhf(gg);
        float hh = so * tanhf(cc);
        out[4 + tid]       = hh;
        out[4 + HID + tid] = cc;
        sm[TI_SX + tid] = hh;
    }
    __syncthreads();
    if (tid < A)
        sm[TI_ACC + tid] = (sm[TI_ACC + tid] + sm[TI_SCORE + tid]) / sm[TI_RED];
    __syncthreads();

    if (wid < NA) {
        float s = 0.f;
        for (int j = lane; j < A + HID; j += 32) {
            float v = (j < A) ? sm[TI_ACC + j] : sm[TI_SX + j - A];
            s += actor_w[wid * (A + HID) + j] * v;
        }
        #pragma unroll
        for (int off = 16; off; off >>= 1)
            s += __shfl_xor_sync(0xffffffffu, s, off);
        if (lane == 0) out[wid] = s + actor_b[wid];
    }
    if (tid == 0) g_cnt = 0;   // reset for next graph replay
}

// ---------------------------------------------------------------------------
extern "C" void kernel_launch(void* const* d_in, const int* in_sizes, int n_in,
                              void* d_out, int out_size)
{
    const float* img     = (const float*)d_in[0];
    const float* action  = (const float*)d_in[1];
    const float* h0      = (const float*)d_in[2];
    const float* c0      = (const float*)d_in[3];
    const float* conv_w  = (const float*)d_in[4];
    const float* conv_b  = (const float*)d_in[5];
    const float* ae_w    = (const float*)d_in[6];
    const float* ae_b    = (const float*)d_in[7];
    const float* ia_w    = (const float*)d_in[8];
    const float* ia_b    = (const float*)d_in[9];
    // d_in[10] ha_w, d_in[11] ha_b, d_in[13] fa_b: softmax-invariant, unused
    const float* fa_w    = (const float*)d_in[12];
    const float* w_ih    = (const float*)d_in[14];
    const float* w_hh    = (const float*)d_in[15];
    const float* b_ih    = (const float*)d_in[16];
    const float* b_hh    = (const float*)d_in[17];
    const float* actor_w = (const float*)d_in[18];
    const float* actor_b = (const float*)d_in[19];
    float* out = (float*)d_out;

    cudaFuncSetAttribute(attn_kernel,
                         cudaFuncAttributeMaxDynamicSharedMemorySize, SMEM_BYTES);

    attn_kernel<<<GRID, NTHREADS, SMEM_BYTES>>>(img, conv_w, conv_b, ia_w, ia_b, fa_w,
                                                action, h0, ae_w, ae_b,
                                                w_ih, w_hh, b_ih, b_hh,
                                                c0, actor_w, actor_b, out);
}

// round 7
// speedup vs baseline: 1.0746x; 1.0746x over previous
#include <cuda_runtime.h>
#include <cuda_fp16.h>
#include <math.h>
#include <stdint.h>

#define C     64
#define A     128
#define HID   256
#define NA    4
#define HW    512
#define NPOS  (HW * HW)
#define TM    128
#define NTILES (NPOS / TM)       // 2048
#define GRID  148
#define NTHREADS 256

// ---- dynamic SMEM byte offsets ----
#define OFF_IMGA  0              // 16384 B (A-frag img, buffer A)
#define OFF_IMGB  16384          // 16384 B (buffer B)
#define OFF_B1    32768          // 4 ks * 8 ntp * 512 = 16384 B (paired layout)
#define OFF_B2    49152          // 8 ks * 8 ntp * 512 = 32768 B
#define OFF_TAIL  81920
#define TF_BASE   (OFF_TAIL / 4)
#define TI_RED    (TF_BASE + 0)      // 16 (l accum + merge L)
#define TI_CB     (TF_BASE + 16)     // 128
#define TI_IB     (TF_BASE + 144)    // 128
#define TI_FW     (TF_BASE + 272)    // 128
#define TI_ACC    (TF_BASE + 400)    // 128 (CTA att partials; merge att)
#define TI_SC2    (TF_BASE + 528)    // 128 (merge half-1 scratch)
#define TI_SX     (TF_BASE + 656)    // 256 (gates x; merge h)
#define TI_SH     (TF_BASE + 912)    // 256 (gates h0)
#define SMEM_BYTES (OFF_TAIL + 1168 * 4)

__device__ float g_l[GRID];
__device__ float g_acc[GRID * A];
__device__ float g_gates[4 * HID];
__device__ unsigned int g_cnt;       // zero-init; last CTA resets after merge

__device__ __forceinline__ void mma16(float* c, const uint32_t* a, const uint32_t* b) {
    asm volatile("mma.sync.aligned.m16n8k16.row.col.f32.f16.f16.f32 "
        "{%0,%1,%2,%3}, {%4,%5,%6,%7}, {%8,%9}, {%0,%1,%2,%3};"
        : "+f"(c[0]), "+f"(c[1]), "+f"(c[2]), "+f"(c[3])
        : "r"(a[0]), "r"(a[1]), "r"(a[2]), "r"(a[3]), "r"(b[0]), "r"(b[1]));
}

__device__ __forceinline__ uint32_t h2(float lo, float hi) {
    __half2 v = __floats2half2_rn(lo, hi);
    return *reinterpret_cast<uint32_t*>(&v);
}

// ---------------------------------------------------------------------------
// Persistent fused kernel, warp-owns-full-N layout (8 M-warps x 128 cols).
// One __syncthreads per tile (img double-buffered); GEMM1->GEMM2 feat handoff
// is pure in-register repack; softmax + pooling fully warp-local.
// Blocks 0..127 also compute LSTM gate rows; last CTA merges + LSTM + logits.
// ---------------------------------------------------------------------------
__global__ void __launch_bounds__(NTHREADS, 1)
attn_kernel(const float* __restrict__ img,
            const float* __restrict__ conv_w, const float* __restrict__ conv_b,
            const float* __restrict__ ia_w,   const float* __restrict__ ia_b,
            const float* __restrict__ fa_w,
            const float* __restrict__ action, const float* __restrict__ h0,
            const float* __restrict__ ae_w,   const float* __restrict__ ae_b,
            const float* __restrict__ w_ih,   const float* __restrict__ w_hh,
            const float* __restrict__ b_ih,   const float* __restrict__ b_hh,
            const float* __restrict__ c0,     const float* __restrict__ actor_w,
            const float* __restrict__ actor_b, float* __restrict__ out)
{
    extern __shared__ __align__(1024) float sm[];
    char* smc = (char*)sm;
    __shared__ unsigned int s_isLast;

    const int tid  = threadIdx.x;
    const int lane = tid & 31;
    const int wid  = tid >> 5;        // 8 M-warps; warp owns rows wid*16..+15
    const int tig  = lane & 3;

    // ---- one-time: pack B1 (conv_w [128n x 64k]) paired-nt fp16 frags ----
    for (int idx = tid; idx < 4 * 16 * 32 * 2; idx += NTHREADS) {
        int r = idx & 1, l = (idx >> 1) & 31, nt = (idx >> 6) & 15, ks = idx >> 10;
        int n = nt * 8 + (l >> 2);
        int k0 = ks * 16 + (l & 3) * 2 + r * 8;
        *(uint32_t*)(smc + OFF_B1 + (ks * 8 + (nt >> 1)) * 512 + l * 16 + (nt & 1) * 8 + r * 4) =
            h2(conv_w[n * C + k0], conv_w[n * C + k0 + 1]);
    }
    // ---- pack B2 (ia_w [128n x 128k]) ----
    for (int idx = tid; idx < 8 * 16 * 32 * 2; idx += NTHREADS) {
        int r = idx & 1, l = (idx >> 1) & 31, nt = (idx >> 6) & 15, ks = idx >> 10;
        int n = nt * 8 + (l >> 2);
        int k0 = ks * 16 + (l & 3) * 2 + r * 8;
        *(uint32_t*)(smc + OFF_B2 + (ks * 8 + (nt >> 1)) * 512 + l * 16 + (nt & 1) * 8 + r * 4) =
            h2(ia_w[n * A + k0], ia_w[n * A + k0 + 1]);
    }
    if (tid < A) {
        sm[TI_CB + tid] = conv_b[tid];
        sm[TI_IB + tid] = ia_b[tid];
        sm[TI_FW + tid] = fa_w[tid];
        sm[TI_ACC + tid] = 0.f;
    }
    if (tid < 16) sm[TI_RED + tid] = 0.f;
    if (blockIdx.x < 128) {     // gates: x = ae(action) + ae_b, stash h0
        float a0 = action[0], a1 = action[1], a2 = action[2], a3 = action[3];
        sm[TI_SX + tid] = ae_b[tid] + a0 * ae_w[tid * 4] + a1 * ae_w[tid * 4 + 1]
                                    + a2 * ae_w[tid * 4 + 2] + a3 * ae_w[tid * 4 + 3];
        sm[TI_SH + tid] = h0[tid];
    }
    __syncthreads();

    // ---- folded LSTM gates: one row per warp for blocks < 128 ----
    if (blockIdx.x < 128) {
        int r = blockIdx.x * 8 + wid;
        const float4* wi = (const float4*)(w_ih + (size_t)r * HID);
        const float4* wh = (const float4*)(w_hh + (size_t)r * HID);
        float s = 0.f;
        #pragma unroll
        for (int j = 0; j < 2; ++j) {
            float4 u = wi[lane * 2 + j], v = wh[lane * 2 + j];
            int k = lane * 8 + j * 4;
            s += u.x * sm[TI_SX + k] + u.y * sm[TI_SX + k + 1]
               + u.z * sm[TI_SX + k + 2] + u.w * sm[TI_SX + k + 3];
            s += v.x * sm[TI_SH + k] + v.y * sm[TI_SH + k + 1]
               + v.z * sm[TI_SH + k + 2] + v.w * sm[TI_SH + k + 3];
        }
        #pragma unroll
        for (int off = 16; off; off >>= 1) s += __shfl_xor_sync(0xffffffffu, s, off);
        if (lane == 0) g_gates[r] = s + b_ih[r] + b_hh[r];
    }

    // staging mapping: thread owns position sp, channels sch*32..+31
    const int sp  = tid & 127, sch = tid >> 7;
    const int smt = sp >> 4, sg = sp & 7, srh = (sp >> 3) & 1;

    float attreg[16][2];
    #pragma unroll
    for (int i = 0; i < 16; ++i) { attreg[i][0] = 0.f; attreg[i][1] = 0.f; }
    float l_run = 0.f;

    // prologue prefetch (tile blockIdx.x), converted to half2 at load
    uint32_t rimg[16];
    {
        const float* srcb = img + (size_t)(sch * 32) * NPOS + (size_t)blockIdx.x * TM + sp;
        #pragma unroll
        for (int j = 0; j < 16; ++j)
            rimg[j] = h2(srcb[(size_t)(2 * j) * NPOS], srcb[(size_t)(2 * j + 1) * NPOS]);
    }

    int it = 0;
    for (int t = blockIdx.x; t < NTILES; t += GRID, ++it) {
        char* imgb = smc + ((it & 1) ? OFF_IMGB : OFF_IMGA);

        // ---- stage img tile into fp16 A fragments (double-buffered) ----
        #pragma unroll
        for (int j = 0; j < 16; ++j) {
            int ks  = sch * 2 + (j >> 3);
            int tg  = j & 3;
            int hb  = (j >> 2) & 1;
            int reg = srh + 2 * hb;
            *(uint32_t*)(imgb + (ks * 8 + smt) * 512 + (sg * 4 + tg) * 16 + reg * 4) = rimg[j];
        }
        __syncthreads();                 // the ONLY per-tile barrier

        // prefetch next tile (hidden under both GEMMs)
        int t2 = t + GRID;
        if (t2 < NTILES) {
            const float* srcb = img + (size_t)(sch * 32) * NPOS + (size_t)t2 * TM + sp;
            #pragma unroll
            for (int j = 0; j < 16; ++j)
                rimg[j] = h2(srcb[(size_t)(2 * j) * NPOS], srcb[(size_t)(2 * j + 1) * NPOS]);
        }

        // ---- GEMM1: feat = img @ conv_w^T  (warp: 16 rows x 128 cols, K=64) ----
        float acc[16][4];
        #pragma unroll
        for (int nt = 0; nt < 16; ++nt)
            #pragma unroll
            for (int r = 0; r < 4; ++r) acc[nt][r] = 0.f;

        #pragma unroll
        for (int ks = 0; ks < 4; ++ks) {
            uint4 av = *(const uint4*)(imgb + (ks * 8 + wid) * 512 + lane * 16);
            uint32_t a[4] = {av.x, av.y, av.z, av.w};
            #pragma unroll
            for (int ntp = 0; ntp < 8; ++ntp) {
                uint4 bv = *(const uint4*)(smc + OFF_B1 + (ks * 8 + ntp) * 512 + lane * 16);
                uint32_t b0[2] = {bv.x, bv.y};
                uint32_t b1[2] = {bv.z, bv.w};
                mma16(acc[ntp * 2],     a, b0);
                mma16(acc[ntp * 2 + 1], a, b1);
            }
        }

        // ---- epilogue 1: bias+relu; in-register repack to GEMM2 A-frags ----
        #pragma unroll
        for (int nt = 0; nt < 16; ++nt) {
            float b0 = sm[TI_CB + nt * 8 + tig * 2];
            float b1 = sm[TI_CB + nt * 8 + tig * 2 + 1];
            acc[nt][0] = fmaxf(acc[nt][0] + b0, 0.f);
            acc[nt][1] = fmaxf(acc[nt][1] + b1, 0.f);
            acc[nt][2] = fmaxf(acc[nt][2] + b0, 0.f);
            acc[nt][3] = fmaxf(acc[nt][3] + b1, 0.f);
        }
        uint32_t af[8][4];
        #pragma unroll
        for (int ks = 0; ks < 8; ++ks) {
            af[ks][0] = h2(acc[ks * 2][0],     acc[ks * 2][1]);      // row g,   k-lo
            af[ks][1] = h2(acc[ks * 2][2],     acc[ks * 2][3]);      // row g+8, k-lo
            af[ks][2] = h2(acc[ks * 2 + 1][0], acc[ks * 2 + 1][1]);  // row g,   k-hi
            af[ks][3] = h2(acc[ks * 2 + 1][2], acc[ks * 2 + 1][3]);  // row g+8, k-hi
        }

        // ---- GEMM2: att1 = feat @ ia_w^T  (A straight from af regs, K=128) ----
        #pragma unroll
        for (int nt = 0; nt < 16; ++nt)
            #pragma unroll
            for (int r = 0; r < 4; ++r) acc[nt][r] = 0.f;

        #pragma unroll
        for (int ks = 0; ks < 8; ++ks) {
            #pragma unroll
            for (int ntp = 0; ntp < 8; ++ntp) {
                uint4 bv = *(const uint4*)(smc + OFF_B2 + (ks * 8 + ntp) * 512 + lane * 16);
                uint32_t b0[2] = {bv.x, bv.y};
                uint32_t b1[2] = {bv.z, bv.w};
                mma16(acc[ntp * 2],     af[ks], b0);
                mma16(acc[ntp * 2 + 1], af[ks], b1);
            }
        }

        // ---- warp-local scores: s[row] = sum_j relu(att1 + ia_b) * fa_w ----
        float s0 = 0.f, s1 = 0.f;
        #pragma unroll
        for (int nt = 0; nt < 16; ++nt) {
            int n0 = nt * 8 + tig * 2;
            float ib0 = sm[TI_IB + n0], ib1 = sm[TI_IB + n0 + 1];
            float fw0 = sm[TI_FW + n0], fw1 = sm[TI_FW + n0 + 1];
            s0 += fmaxf(acc[nt][0] + ib0, 0.f) * fw0 + fmaxf(acc[nt][1] + ib1, 0.f) * fw1;
            s1 += fmaxf(acc[nt][2] + ib0, 0.f) * fw0 + fmaxf(acc[nt][3] + ib1, 0.f) * fw1;
        }
        s0 += __shfl_xor_sync(0xffffffffu, s0, 1);
        s0 += __shfl_xor_sync(0xffffffffu, s0, 2);
        s1 += __shfl_xor_sync(0xffffffffu, s1, 1);
        s1 += __shfl_xor_sync(0xffffffffu, s1, 2);

        // max-free softmax weights (scores bounded far below exp overflow)
        float w0 = expf(s0), w1 = expf(s1);
        float v = w0 + w1;
        v += __shfl_xor_sync(0xffffffffu, v, 4);
        v += __shfl_xor_sync(0xffffffffu, v, 8);
        v += __shfl_xor_sync(0xffffffffu, v, 16);
        l_run += v;   // per-lane identical; lane 0's used at CTA end

        // ---- warp-local pooling from af registers (fp16 feat) ----
        #pragma unroll
        for (int ks = 0; ks < 8; ++ks) {
            float2 f;
            f = __half22float2(*(__half2*)&af[ks][0]);   // nt=2ks, row g
            attreg[ks * 2][0] += w0 * f.x;  attreg[ks * 2][1] += w0 * f.y;
            f = __half22float2(*(__half2*)&af[ks][1]);   // nt=2ks, row g+8
            attreg[ks * 2][0] += w1 * f.x;  attreg[ks * 2][1] += w1 * f.y;
            f = __half22float2(*(__half2*)&af[ks][2]);   // nt=2ks+1, row g
            attreg[ks * 2 + 1][0] += w0 * f.x;  attreg[ks * 2 + 1][1] += w0 * f.y;
            f = __half22float2(*(__half2*)&af[ks][3]);   // nt=2ks+1, row g+8
            attreg[ks * 2 + 1][0] += w1 * f.x;  attreg[ks * 2 + 1][1] += w1 * f.y;
        }
    }

    // ---- CTA epilogue: reduce attreg over groups, emit partials ----
    __syncthreads();
    #pragma unroll
    for (int nt = 0; nt < 16; ++nt) {
        #pragma unroll
        for (int cc = 0; cc < 2; ++cc) {
            float v = attreg[nt][cc];
            v += __shfl_xor_sync(0xffffffffu, v, 4);
            v += __shfl_xor_sync(0xffffffffu, v, 8);
            v += __shfl_xor_sync(0xffffffffu, v, 16);
            if (lane < 4) atomicAdd(&sm[TI_ACC + nt * 8 + lane * 2 + cc], v);
        }
    }
    if (lane == 0) atomicAdd(&sm[TI_RED], l_run);
    __syncthreads();
    if (tid < A) g_acc[blockIdx.x * A + tid] = sm[TI_ACC + tid];
    if (tid == 0) g_l[blockIdx.x] = sm[TI_RED];

    // ---- last-CTA merge: softmax normalize + LSTM + logits ----
    __threadfence();
    __syncthreads();
    if (tid == 0) s_isLast = (atomicAdd(&g_cnt, 1u) == GRID - 1);
    __syncthreads();
    if (!s_isLast) return;
    __threadfence();

    // L = sum g_l
    if (wid == 0) {
        float l = 0.f;
        for (int b = lane; b < GRID; b += 32) l += g_l[b];
        #pragma unroll
        for (int off = 16; off; off >>= 1)
            l += __shfl_xor_sync(0xffffffffu, l, off);
        if (lane == 0) sm[TI_RED + 8] = l;
    }
    // half-column partial sums of g_acc (2 threads per column, MLP-rich)
    {
        int a = tid & 127, hh = tid >> 7;
        const float* src = g_acc + (size_t)(hh * (GRID / 2)) * A + a;
        float p = 0.f;
        #pragma unroll 4
        for (int b = 0; b < GRID / 2; ++b) p += src[(size_t)b * A];
        sm[(hh ? TI_SC2 : TI_ACC) + a] = p;
    }
    // LSTM activations from g_gates
    {
        float ig = g_gates[tid];
        float fg = g_gates[HID + tid];
        float gg = g_gates[2 * HID + tid];
        float og = g_gates[3 * HID + tid];
        float si = 1.f / (1.f + expf(-ig));
        float sf = 1.f / (1.f + expf(-fg));
        float so = 1.f / (1.f + expf(-og));
        float cc = sf * c0[tid] + si * tanhf(gg);
        float hh = so * tanhf(cc);
        out[4 + tid]       = hh;
        out[4 + HID + tid] = cc;
        sm[TI_SX + tid] = hh;
    }
    __syncthreads();
    if (tid < A)
        sm[TI_ACC + tid] = (sm[TI_ACC + tid] + sm[TI_SC2 + tid]) / sm[TI_RED + 8];
    __syncthreads();

    if (wid < NA) {
        float s = 0.f;
        for (int j = lane; j < A + HID; j += 32) {
            float v = (j < A) ? sm[TI_ACC + j] : sm[TI_SX + j - A];
            s += actor_w[wid * (A + HID) + j] * v;
        }
        #pragma unroll
        for (int off = 16; off; off >>= 1)
            s += __shfl_xor_sync(0xffffffffu, s, off);
        if (lane == 0) out[wid] = s + actor_b[wid];
    }
    if (tid == 0) g_cnt = 0;   // reset for next graph replay
}

// ---------------------------------------------------------------------------
extern "C" void kernel_launch(void* const* d_in, const int* in_sizes, int n_in,
                              void* d_out, int out_size)
{
    const float* img     = (const float*)d_in[0];
    const float* action  = (const float*)d_in[1];
    const float* h0      = (const float*)d_in[2];
    const float* c0      = (const float*)d_in[3];
    const float* conv_w  = (const float*)d_in[4];
    const float* conv_b  = (const float*)d_in[5];
    const float* ae_w    = (const float*)d_in[6];
    const float* ae_b    = (const float*)d_in[7];
    const float* ia_w    = (const float*)d_in[8];
    const float* ia_b    = (const float*)d_in[9];
    // d_in[10] ha_w, d_in[11] ha_b, d_in[13] fa_b: softmax-invariant, unused
    const float* fa_w    = (const float*)d_in[12];
    const float* w_ih    = (const float*)d_in[14];
    const float* w_hh    = (const float*)d_in[15];
    const float* b_ih    = (const float*)d_in[16];
    const float* b_hh    = (const float*)d_in[17];
    const float* actor_w = (const float*)d_in[18];
    const float* actor_b = (const float*)d_in[19];
    float* out = (float*)d_out;

    cudaFuncSetAttribute(attn_kernel,
                         cudaFuncAttributeMaxDynamicSharedMemorySize, SMEM_BYTES);

    attn_kernel<<<GRID, NTHREADS, SMEM_BYTES>>>(img, conv_w, conv_b, ia_w, ia_b, fa_w,
                                                action, h0, ae_w, ae_b,
                                                w_ih, w_hh, b_ih, b_hh,
                                                c0, actor_w, actor_b, out);
}